// round 2
// baseline (speedup 1.0000x reference)
#include <cuda_runtime.h>

#define N_SRC0 100000
#define N_DST0 20000
#define N_DST1 4000
#define E0V 640000
#define E1V 128000
#define IN_F 512
#define HID_F 512
#define OUT_F 256

// ---------------- scratch layout (floats, single __device__ arena) ----------
#define OFF_AGG0  ((size_t)0)
#define SZ_AGG0   ((size_t)N_DST0 * IN_F)          // 10,240,000
#define OFF_AGG1  (OFF_AGG0 + SZ_AGG0)
#define SZ_AGG1   ((size_t)N_DST1 * HID_F)         //  2,048,000
#define OFF_DOUT0 (OFF_AGG1 + SZ_AGG1)
#define OFF_DIN0  (OFF_DOUT0 + N_SRC0)
#define OFF_DOUT1 (OFF_DIN0 + N_DST0)
#define OFF_DIN1  (OFF_DOUT1 + N_DST0)
#define N_DEG     ((size_t)(N_SRC0 + N_DST0 + N_DST0 + N_DST1))   // 144,000
#define ZERO_TOTAL (OFF_DIN1 + N_DST1)             // 12,432,000 (div by 4)
#define OFF_H1    ZERO_TOTAL
#define SZ_H1     ((size_t)N_DST0 * HID_F)
#define TOTAL_SCRATCH (OFF_H1 + SZ_H1)             // ~90.7 MB

__device__ float g_scratch[TOTAL_SCRATCH];

// ---------------- kernels ---------------------------------------------------

__global__ void k_zero(float4* __restrict__ p, int n4) {
    int stride = gridDim.x * blockDim.x;
    for (int i = blockIdx.x * blockDim.x + threadIdx.x; i < n4; i += stride)
        p[i] = make_float4(0.f, 0.f, 0.f, 0.f);
}

// Degree counts for both layers in one edge-parallel kernel.
__global__ void k_deg(const int* __restrict__ s0, const int* __restrict__ d0,
                      const int* __restrict__ s1, const int* __restrict__ d1,
                      float* __restrict__ base) {
    int i = blockIdx.x * blockDim.x + threadIdx.x;
    if (i < E0V) {
        atomicAdd(base + OFF_DOUT0 + s0[i], 1.0f);
        atomicAdd(base + OFF_DIN0  + d0[i], 1.0f);
    } else {
        int j = i - E0V;
        if (j < E1V) {
            atomicAdd(base + OFF_DOUT1 + s1[j], 1.0f);
            atomicAdd(base + OFF_DIN1  + d1[j], 1.0f);
        }
    }
}

// deg -> rsqrt(max(deg,1)) in place over the whole degree region.
__global__ void k_rsqrt(float* __restrict__ d, int n) {
    int i = blockIdx.x * blockDim.x + threadIdx.x;
    if (i < n) d[i] = rsqrtf(fmaxf(d[i], 1.0f));
}

// Edge-parallel scatter: one warp per edge, F = 512 floats per row.
// agg[dst] += h[src] * outn[src]  via red.global.add.v4.f32 (16B vector REDs).
__global__ void k_scatter(const float* __restrict__ h,
                          const int* __restrict__ src, const int* __restrict__ dst,
                          const float* __restrict__ outn,
                          float* __restrict__ agg, int E) {
    int gt = blockIdx.x * blockDim.x + threadIdx.x;
    int e = gt >> 5;
    int lane = gt & 31;
    if (e >= E) return;
    int s = src[e];
    int d = dst[e];
    float sc = outn[s];
    const float4* hp = reinterpret_cast<const float4*>(h) + (size_t)s * (IN_F / 4) + lane;
    float* ap = agg + (size_t)d * IN_F + lane * 4;
#pragma unroll
    for (int i = 0; i < 4; i++) {
        float4 v = __ldg(hp + i * 32);
        asm volatile("red.global.add.v4.f32 [%0], {%1, %2, %3, %4};"
                     :: "l"(ap + i * 128),
                        "f"(v.x * sc), "f"(v.y * sc), "f"(v.z * sc), "f"(v.w * sc)
                     : "memory");
    }
}

// C = relu( (A * rowscale) @ B + bias ), A:[M,K] row-major, B:[K,N] row-major.
// BM=128, BN=64, BK=16, 256 threads, 8x4 per-thread micro-tile.
__global__ __launch_bounds__(256) void k_gemm(
    const float* __restrict__ A, const float* __restrict__ rs,
    const float* __restrict__ B, const float* __restrict__ bias,
    float* __restrict__ C, int M, int N, int K) {
    const int BM = 128, BN = 64, BK = 16;
    __shared__ float As[BK][BM];   // transposed: As[k][m]
    __shared__ float Bs[BK][BN];

    int tid = threadIdx.x;
    int tx = tid & 15;        // 0..15 -> 4 cols each
    int ty = tid >> 4;        // 0..15 -> 8 rows each
    int row0 = blockIdx.y * BM;
    int col0 = blockIdx.x * BN;

    float acc[8][4];
#pragma unroll
    for (int i = 0; i < 8; i++)
#pragma unroll
        for (int j = 0; j < 4; j++) acc[i][j] = 0.f;

    for (int k0 = 0; k0 < K; k0 += BK) {
        // Stage A tile (128 rows x 16 k), scaled by rs[row], transposed into As.
#pragma unroll
        for (int t = 0; t < 2; t++) {
            int idx = tid + t * 256;          // 0..511
            int r = idx >> 2;                 // 0..127
            int kk = (idx & 3) * 4;           // 0,4,8,12
            int gr = row0 + r;
            float4 v = make_float4(0.f, 0.f, 0.f, 0.f);
            if (gr < M) {
                v = *reinterpret_cast<const float4*>(A + (size_t)gr * K + k0 + kk);
                float sc = rs[gr];
                v.x *= sc; v.y *= sc; v.z *= sc; v.w *= sc;
            }
            As[kk + 0][r] = v.x;
            As[kk + 1][r] = v.y;
            As[kk + 2][r] = v.z;
            As[kk + 3][r] = v.w;
        }
        // Stage B tile (16 k x 64 cols), one float4 per thread.
        {
            int r = tid >> 4;                 // 0..15
            int c = (tid & 15) * 4;           // 0..60
            float4 v = *reinterpret_cast<const float4*>(B + (size_t)(k0 + r) * N + col0 + c);
            *reinterpret_cast<float4*>(&Bs[r][c]) = v;
        }
        __syncthreads();

#pragma unroll
        for (int kk = 0; kk < BK; kk++) {
            float4 a0 = *reinterpret_cast<float4*>(&As[kk][ty * 8]);
            float4 a1 = *reinterpret_cast<float4*>(&As[kk][ty * 8 + 4]);
            float4 bb = *reinterpret_cast<float4*>(&Bs[kk][tx * 4]);
            float a[8] = {a0.x, a0.y, a0.z, a0.w, a1.x, a1.y, a1.z, a1.w};
            float b[4] = {bb.x, bb.y, bb.z, bb.w};
#pragma unroll
            for (int i = 0; i < 8; i++)
#pragma unroll
                for (int j = 0; j < 4; j++)
                    acc[i][j] += a[i] * b[j];
        }
        __syncthreads();
    }

    float4 bv = *reinterpret_cast<const float4*>(bias + col0 + tx * 4);
#pragma unroll
    for (int i = 0; i < 8; i++) {
        int gr = row0 + ty * 8 + i;
        if (gr < M) {
            float4 o;
            o.x = fmaxf(acc[i][0] + bv.x, 0.f);
            o.y = fmaxf(acc[i][1] + bv.y, 0.f);
            o.z = fmaxf(acc[i][2] + bv.z, 0.f);
            o.w = fmaxf(acc[i][3] + bv.w, 0.f);
            *reinterpret_cast<float4*>(C + (size_t)gr * N + col0 + tx * 4) = o;
        }
    }
}

// ---------------- launch ----------------------------------------------------

extern "C" void kernel_launch(void* const* d_in, const int* in_sizes, int n_in,
                              void* d_out, int out_size) {
    const float* x    = (const float*)d_in[0];
    const int*   src0 = (const int*)d_in[1];
    const int*   dst0 = (const int*)d_in[2];
    const int*   src1 = (const int*)d_in[3];
    const int*   dst1 = (const int*)d_in[4];
    const float* W1   = (const float*)d_in[5];
    const float* b1   = (const float*)d_in[6];
    const float* W2   = (const float*)d_in[7];
    const float* b2   = (const float*)d_in[8];
    float* out = (float*)d_out;

    float* base = nullptr;
    cudaGetSymbolAddress((void**)&base, g_scratch);

    // 1) zero accumulators + degree counters
    k_zero<<<2048, 256>>>((float4*)base, (int)(ZERO_TOTAL / 4));

    // 2) degrees for both layers
    k_deg<<<(E0V + E1V + 255) / 256, 256>>>(src0, dst0, src1, dst1, base);

    // 3) deg -> rsqrt(max(deg,1))
    k_rsqrt<<<((int)N_DEG + 255) / 256, 256>>>(base + OFF_DOUT0, (int)N_DEG);

    // 4) layer-1 scatter: agg0[dst] += x[src] * outn0[src]
    k_scatter<<<(E0V * 32 + 255) / 256, 256>>>(x, src0, dst0,
                                               base + OFF_DOUT0, base + OFF_AGG0, E0V);

    // 5) h1 = relu((agg0 * din0^-1/2) @ W1 + b1)
    {
        dim3 grid(HID_F / 64, (N_DST0 + 127) / 128);
        k_gemm<<<grid, 256>>>(base + OFF_AGG0, base + OFF_DIN0, W1, b1,
                              base + OFF_H1, N_DST0, HID_F, IN_F);
    }

    // 6) layer-2 scatter: agg1[dst] += h1[src] * outn1[src]
    k_scatter<<<(E1V * 32 + 255) / 256, 256>>>(base + OFF_H1, src1, dst1,
                                               base + OFF_DOUT1, base + OFF_AGG1, E1V);

    // 7) out = relu((agg1 * din1^-1/2) @ W2 + b2)
    {
        dim3 grid(OUT_F / 64, (N_DST1 + 127) / 128);
        k_gemm<<<grid, 256>>>(base + OFF_AGG1, base + OFF_DIN1, W2, b2,
                              out, N_DST1, OUT_F, HID_F);
    }
}

// round 3
// speedup vs baseline: 1.0977x; 1.0977x over previous
#include <cuda_runtime.h>

#define N_SRC0 100000
#define N_DST0 20000
#define N_DST1 4000
#define E0V 640000
#define E1V 128000
#define IN_F 512
#define HID_F 512
#define OUT_F 256

// ---------------- scratch (device globals) ----------------------------------
__device__ float g_agg0[(size_t)N_DST0 * IN_F];    // 41 MB, zeroed each call
__device__ float g_h1[(size_t)N_DST0 * HID_F];     // fully written by gemm1
__device__ float g_agg1[(size_t)N_DST1 * HID_F];   // fully written by gather
__device__ float g_norm[N_SRC0 + N_DST0 + N_DST0 + N_DST1];   // outn0,din0,outn1,din1

// int block: cnt_src0 | cnt_dst0 | cnt_src1 | cnt_dst1 | cur0 | cur1d
#define OFF_C_SRC0 0
#define OFF_C_DST0 (N_SRC0)
#define OFF_C_SRC1 (N_SRC0 + N_DST0)
#define OFF_C_DST1 (N_SRC0 + 2 * N_DST0)
#define N_CNT      (N_SRC0 + 2 * N_DST0 + N_DST1)           // 144000
#define OFF_CUR0   N_CNT
#define OFF_CUR1   (N_CNT + N_SRC0)
#define N_INTS     (N_CNT + N_SRC0 + N_DST1)                // 248000
__device__ int g_ints[N_INTS];

__device__ int g_rp0[N_SRC0 + 1];
__device__ int g_rp1[N_DST1 + 1];
__device__ int g_col0[E0V];
__device__ int g_col1[E1V];
__device__ int g_part[256];

// ---------------- utility kernels -------------------------------------------

__global__ void k_zero2(float4* __restrict__ a, int n4, int* __restrict__ b, int nb) {
    int stride = gridDim.x * blockDim.x;
    for (int i = blockIdx.x * blockDim.x + threadIdx.x; i < n4; i += stride)
        a[i] = make_float4(0.f, 0.f, 0.f, 0.f);
    for (int i = blockIdx.x * blockDim.x + threadIdx.x; i < nb; i += stride)
        b[i] = 0;
}

// edge-parallel degree counts (ints) for both layers
__global__ void k_count(const int* __restrict__ s0, const int* __restrict__ d0,
                        const int* __restrict__ s1, const int* __restrict__ d1,
                        int* __restrict__ ints) {
    int i = blockIdx.x * blockDim.x + threadIdx.x;
    if (i < E0V) {
        atomicAdd(ints + OFF_C_SRC0 + s0[i], 1);
        atomicAdd(ints + OFF_C_DST0 + d0[i], 1);
    } else {
        int j = i - E0V;
        if (j < E1V) {
            atomicAdd(ints + OFF_C_SRC1 + s1[j], 1);
            atomicAdd(ints + OFF_C_DST1 + d1[j], 1);
        }
    }
}

// norms = rsqrt(max(count,1)); layouts of g_norm and first N_CNT ints match
__global__ void k_norm(const int* __restrict__ ints, float* __restrict__ nrm) {
    int i = blockIdx.x * blockDim.x + threadIdx.x;
    if (i < N_CNT) nrm[i] = rsqrtf(fmaxf((float)ints[i], 1.0f));
}

// ---- 3-phase exclusive scan (counts -> rowptr) ------------------------------
__global__ void k_scan1(const int* __restrict__ cnt, int* __restrict__ rp,
                        int* __restrict__ part, int n) {
    __shared__ int sd[1024];
    int tid = threadIdx.x;
    int i = blockIdx.x * 1024 + tid;
    sd[tid] = (i < n) ? cnt[i] : 0;
    __syncthreads();
#pragma unroll
    for (int d = 1; d < 1024; d <<= 1) {
        int t = (tid >= d) ? sd[tid - d] : 0;
        __syncthreads();
        sd[tid] += t;
        __syncthreads();
    }
    if (i < n) rp[i + 1] = sd[tid];
    if (tid == 1023) part[blockIdx.x] = sd[1023];
}

__global__ void k_scan2(int* __restrict__ part, int nb, int* __restrict__ rp) {
    __shared__ int sd[128];
    int tid = threadIdx.x;
    sd[tid] = (tid < nb) ? part[tid] : 0;
    __syncthreads();
#pragma unroll
    for (int d = 1; d < 128; d <<= 1) {
        int t = (tid >= d) ? sd[tid - d] : 0;
        __syncthreads();
        sd[tid] += t;
        __syncthreads();
    }
    if (tid < nb) part[tid] = (tid == 0) ? 0 : sd[tid - 1];   // exclusive
    if (tid == 0) rp[0] = 0;
}

__global__ void k_scan3(int* __restrict__ rp, const int* __restrict__ part, int n) {
    int b = blockIdx.x;
    if (b == 0) return;
    int i = b * 1024 + threadIdx.x;
    if (i < n) rp[i + 1] += part[b];
}

// counting-sort fill: col[rp[key]+cursor++] = val
__global__ void k_fill(const int* __restrict__ key, const int* __restrict__ val,
                       const int* __restrict__ rp, int* __restrict__ cur,
                       int* __restrict__ col, int E) {
    int i = blockIdx.x * blockDim.x + threadIdx.x;
    if (i < E) {
        int k = key[i];
        int pos = rp[k] + atomicAdd(cur + k, 1);
        col[pos] = val[i];
    }
}

// ---------------- layer-1: CSR-by-src scatter (read x once, RED into L2) ----
__global__ void k_scatter_src(const float* __restrict__ x,
                              const int* __restrict__ rp, const int* __restrict__ col,
                              const float* __restrict__ outn,
                              float* __restrict__ agg, int n_src) {
    int w = (blockIdx.x * blockDim.x + threadIdx.x) >> 5;
    int lane = threadIdx.x & 31;
    if (w >= n_src) return;
    int beg = rp[w], end = rp[w + 1];
    if (beg == end) return;
    float sc = outn[w];
    const float4* xp = reinterpret_cast<const float4*>(x) + (size_t)w * (IN_F / 4) + lane;
    float4 v0 = xp[0], v1 = xp[32], v2 = xp[64], v3 = xp[96];
    v0.x *= sc; v0.y *= sc; v0.z *= sc; v0.w *= sc;
    v1.x *= sc; v1.y *= sc; v1.z *= sc; v1.w *= sc;
    v2.x *= sc; v2.y *= sc; v2.z *= sc; v2.w *= sc;
    v3.x *= sc; v3.y *= sc; v3.z *= sc; v3.w *= sc;
    for (int e = beg; e < end; e++) {
        int d = __ldg(col + e);
        float* ap = agg + (size_t)d * IN_F + lane * 4;
        asm volatile("red.global.add.v4.f32 [%0], {%1, %2, %3, %4};"
                     :: "l"(ap), "f"(v0.x), "f"(v0.y), "f"(v0.z), "f"(v0.w) : "memory");
        asm volatile("red.global.add.v4.f32 [%0], {%1, %2, %3, %4};"
                     :: "l"(ap + 128), "f"(v1.x), "f"(v1.y), "f"(v1.z), "f"(v1.w) : "memory");
        asm volatile("red.global.add.v4.f32 [%0], {%1, %2, %3, %4};"
                     :: "l"(ap + 256), "f"(v2.x), "f"(v2.y), "f"(v2.z), "f"(v2.w) : "memory");
        asm volatile("red.global.add.v4.f32 [%0], {%1, %2, %3, %4};"
                     :: "l"(ap + 384), "f"(v3.x), "f"(v3.y), "f"(v3.z), "f"(v3.w) : "memory");
    }
}

// ---------------- layer-2: CSR-by-dst gather (no atomics, h1 lives in L2) ---
__global__ void k_gather_dst(const float* __restrict__ h,
                             const int* __restrict__ rp, const int* __restrict__ col,
                             const float* __restrict__ outn,
                             float* __restrict__ agg, int n_dst) {
    int w = (blockIdx.x * blockDim.x + threadIdx.x) >> 5;
    int lane = threadIdx.x & 31;
    if (w >= n_dst) return;
    int beg = rp[w], end = rp[w + 1];
    float4 a0 = make_float4(0.f, 0.f, 0.f, 0.f);
    float4 a1 = a0, a2 = a0, a3 = a0;
    for (int e = beg; e < end; e++) {
        int s = __ldg(col + e);
        float sc = __ldg(outn + s);
        const float4* hp = reinterpret_cast<const float4*>(h) + (size_t)s * (HID_F / 4) + lane;
        float4 v0 = __ldg(hp), v1 = __ldg(hp + 32), v2 = __ldg(hp + 64), v3 = __ldg(hp + 96);
        a0.x = fmaf(v0.x, sc, a0.x); a0.y = fmaf(v0.y, sc, a0.y);
        a0.z = fmaf(v0.z, sc, a0.z); a0.w = fmaf(v0.w, sc, a0.w);
        a1.x = fmaf(v1.x, sc, a1.x); a1.y = fmaf(v1.y, sc, a1.y);
        a1.z = fmaf(v1.z, sc, a1.z); a1.w = fmaf(v1.w, sc, a1.w);
        a2.x = fmaf(v2.x, sc, a2.x); a2.y = fmaf(v2.y, sc, a2.y);
        a2.z = fmaf(v2.z, sc, a2.z); a2.w = fmaf(v2.w, sc, a2.w);
        a3.x = fmaf(v3.x, sc, a3.x); a3.y = fmaf(v3.y, sc, a3.y);
        a3.z = fmaf(v3.z, sc, a3.z); a3.w = fmaf(v3.w, sc, a3.w);
    }
    float4* ap = reinterpret_cast<float4*>(agg) + (size_t)w * (HID_F / 4) + lane;
    ap[0] = a0; ap[32] = a1; ap[64] = a2; ap[96] = a3;
}

// ---------------- GEMM: C = relu((A*rowscale) @ B + bias) --------------------
__global__ __launch_bounds__(256) void k_gemm(
    const float* __restrict__ A, const float* __restrict__ rs,
    const float* __restrict__ B, const float* __restrict__ bias,
    float* __restrict__ C, int M, int N, int K) {
    const int BM = 128, BN = 64, BK = 16;
    __shared__ float As[BK][BM];
    __shared__ float Bs[BK][BN];

    int tid = threadIdx.x;
    int tx = tid & 15;
    int ty = tid >> 4;
    int row0 = blockIdx.y * BM;
    int col0 = blockIdx.x * BN;

    float acc[8][4];
#pragma unroll
    for (int i = 0; i < 8; i++)
#pragma unroll
        for (int j = 0; j < 4; j++) acc[i][j] = 0.f;

    for (int k0 = 0; k0 < K; k0 += BK) {
#pragma unroll
        for (int t = 0; t < 2; t++) {
            int idx = tid + t * 256;
            int r = idx >> 2;
            int kk = (idx & 3) * 4;
            int gr = row0 + r;
            float4 v = make_float4(0.f, 0.f, 0.f, 0.f);
            if (gr < M) {
                v = *reinterpret_cast<const float4*>(A + (size_t)gr * K + k0 + kk);
                float sc = rs[gr];
                v.x *= sc; v.y *= sc; v.z *= sc; v.w *= sc;
            }
            As[kk + 0][r] = v.x;
            As[kk + 1][r] = v.y;
            As[kk + 2][r] = v.z;
            As[kk + 3][r] = v.w;
        }
        {
            int r = tid >> 4;
            int c = (tid & 15) * 4;
            float4 v = *reinterpret_cast<const float4*>(B + (size_t)(k0 + r) * N + col0 + c);
            *reinterpret_cast<float4*>(&Bs[r][c]) = v;
        }
        __syncthreads();

#pragma unroll
        for (int kk = 0; kk < BK; kk++) {
            float4 a0 = *reinterpret_cast<float4*>(&As[kk][ty * 8]);
            float4 a1 = *reinterpret_cast<float4*>(&As[kk][ty * 8 + 4]);
            float4 bb = *reinterpret_cast<float4*>(&Bs[kk][tx * 4]);
            float a[8] = {a0.x, a0.y, a0.z, a0.w, a1.x, a1.y, a1.z, a1.w};
            float b[4] = {bb.x, bb.y, bb.z, bb.w};
#pragma unroll
            for (int i = 0; i < 8; i++)
#pragma unroll
                for (int j = 0; j < 4; j++)
                    acc[i][j] += a[i] * b[j];
        }
        __syncthreads();
    }

    float4 bv = *reinterpret_cast<const float4*>(bias + col0 + tx * 4);
#pragma unroll
    for (int i = 0; i < 8; i++) {
        int gr = row0 + ty * 8 + i;
        if (gr < M) {
            float4 o;
            o.x = fmaxf(acc[i][0] + bv.x, 0.f);
            o.y = fmaxf(acc[i][1] + bv.y, 0.f);
            o.z = fmaxf(acc[i][2] + bv.z, 0.f);
            o.w = fmaxf(acc[i][3] + bv.w, 0.f);
            *reinterpret_cast<float4*>(C + (size_t)gr * N + col0 + tx * 4) = o;
        }
    }
}

// ---------------- launch ----------------------------------------------------

extern "C" void kernel_launch(void* const* d_in, const int* in_sizes, int n_in,
                              void* d_out, int out_size) {
    const float* x    = (const float*)d_in[0];
    const int*   src0 = (const int*)d_in[1];
    const int*   dst0 = (const int*)d_in[2];
    const int*   src1 = (const int*)d_in[3];
    const int*   dst1 = (const int*)d_in[4];
    const float* W1   = (const float*)d_in[5];
    const float* b1   = (const float*)d_in[6];
    const float* W2   = (const float*)d_in[7];
    const float* b2   = (const float*)d_in[8];
    float* out = (float*)d_out;

    float *agg0, *h1, *agg1, *nrm;
    int *ints, *rp0, *rp1, *col0, *col1, *part;
    cudaGetSymbolAddress((void**)&agg0, g_agg0);
    cudaGetSymbolAddress((void**)&h1,   g_h1);
    cudaGetSymbolAddress((void**)&agg1, g_agg1);
    cudaGetSymbolAddress((void**)&nrm,  g_norm);
    cudaGetSymbolAddress((void**)&ints, g_ints);
    cudaGetSymbolAddress((void**)&rp0,  g_rp0);
    cudaGetSymbolAddress((void**)&rp1,  g_rp1);
    cudaGetSymbolAddress((void**)&col0, g_col0);
    cudaGetSymbolAddress((void**)&col1, g_col1);
    cudaGetSymbolAddress((void**)&part, g_part);

    const float* outn0 = nrm + OFF_C_SRC0;   // rsqrt(out_deg0), n_src0
    const float* din0  = nrm + OFF_C_DST0;   // rsqrt(in_deg0),  n_dst0
    const float* outn1 = nrm + OFF_C_SRC1;   // rsqrt(out_deg1), n_dst0
    const float* din1  = nrm + OFF_C_DST1;   // rsqrt(in_deg1),  n_dst1

    // 1) zero agg0 + all int counters/cursors
    k_zero2<<<2048, 256>>>((float4*)agg0, (int)((size_t)N_DST0 * IN_F / 4), ints, N_INTS);

    // 2) integer degree counts (both layers)
    k_count<<<(E0V + E1V + 255) / 256, 256>>>(src0, dst0, src1, dst1, ints);

    // 3) norms from counts
    k_norm<<<(N_CNT + 255) / 256, 256>>>(ints, nrm);

    // 4) CSR layer-1 by src: rowptr0 over n_src0
    {
        int nb = (N_SRC0 + 1023) / 1024;  // 98
        k_scan1<<<nb, 1024>>>(ints + OFF_C_SRC0, rp0, part, N_SRC0);
        k_scan2<<<1, 128>>>(part, nb, rp0);
        k_scan3<<<nb, 1024>>>(rp0, part, N_SRC0);
        k_fill<<<(E0V + 255) / 256, 256>>>(src0, dst0, rp0, ints + OFF_CUR0, col0, E0V);
    }

    // 5) CSR layer-2 by dst: rowptr1 over n_dst1
    {
        int nb = (N_DST1 + 1023) / 1024;  // 4
        k_scan1<<<nb, 1024>>>(ints + OFF_C_DST1, rp1, part, N_DST1);
        k_scan2<<<1, 128>>>(part, nb, rp1);
        k_scan3<<<nb, 1024>>>(rp1, part, N_DST1);
        k_fill<<<(E1V + 255) / 256, 256>>>(dst1, src1, rp1, ints + OFF_CUR1, col1, E1V);
    }

    // 6) layer-1 scatter: read each x row once, RED into L2-resident agg0
    k_scatter_src<<<(N_SRC0 * 32 + 255) / 256, 256>>>(x, rp0, col0, outn0, agg0, N_SRC0);

    // 7) h1 = relu((agg0 * din0) @ W1 + b1)
    {
        dim3 grid(HID_F / 64, (N_DST0 + 127) / 128);
        k_gemm<<<grid, 256>>>(agg0, din0, W1, b1, h1, N_DST0, HID_F, IN_F);
    }

    // 8) layer-2 gather (h1 fits L2): agg1[d] = sum h1[s]*outn1[s]
    k_gather_dst<<<(N_DST1 * 32 + 255) / 256, 256>>>(h1, rp1, col1, outn1, agg1, N_DST1);

    // 9) out = relu((agg1 * din1) @ W2 + b2)
    {
        dim3 grid(OUT_F / 64, (N_DST1 + 127) / 128);
        k_gemm<<<grid, 256>>>(agg1, din1, W2, b2, out, N_DST1, OUT_F, HID_F);
    }
}

// round 7
// speedup vs baseline: 1.4518x; 1.3226x over previous
#include <cuda_runtime.h>
#include <cuda_bf16.h>
#include <cstdint>

#define N_SRC0 100000
#define N_DST0 20000
#define N_DST1 4000
#define E0V 640000
#define E1V 128000
#define IN_F 512
#define HID_F 512
#define OUT_F 256

#define MPAD1 20096          // 157 * 128
#define MPAD2 4096           // 32 * 128

// ---------------- scratch (device globals) ----------------------------------
__device__ float g_agg0[(size_t)N_DST0 * IN_F];
__device__ float g_h1[(size_t)N_DST0 * HID_F];
__device__ float g_agg1[(size_t)N_DST1 * HID_F];
__device__ float g_norm[N_SRC0 + N_DST0 + N_DST0 + N_DST1];

#define OFF_C_SRC0 0
#define OFF_C_DST0 (N_SRC0)
#define OFF_C_SRC1 (N_SRC0 + N_DST0)
#define OFF_C_DST1 (N_SRC0 + 2 * N_DST0)
#define N_CNT      (N_SRC0 + 2 * N_DST0 + N_DST1)
#define OFF_CUR0   N_CNT
#define OFF_CUR1   (N_CNT + N_SRC0)
#define N_INTS     (N_CNT + N_SRC0 + N_DST1)
__device__ int g_ints[N_INTS];

__device__ int g_rp0[N_SRC0 + 1];
__device__ int g_rp1[N_DST1 + 1];
__device__ int g_col0[E0V];
__device__ int g_col1[E1V];
__device__ int g_part[256];

// bf16 split operands
__device__ __nv_bfloat16 g_a1hi[(size_t)MPAD1 * 512];
__device__ __nv_bfloat16 g_a1lo[(size_t)MPAD1 * 512];
__device__ __nv_bfloat16 g_a2hi[(size_t)MPAD2 * 512];
__device__ __nv_bfloat16 g_a2lo[(size_t)MPAD2 * 512];
__device__ __nv_bfloat16 g_w1hi[512 * 512];
__device__ __nv_bfloat16 g_w1lo[512 * 512];
__device__ __nv_bfloat16 g_w2hi[256 * 512];
__device__ __nv_bfloat16 g_w2lo[256 * 512];

// ---------------- utility kernels -------------------------------------------

__global__ void k_zero2(float4* __restrict__ a, int n4, int* __restrict__ b, int nb) {
    int stride = gridDim.x * blockDim.x;
    for (int i = blockIdx.x * blockDim.x + threadIdx.x; i < n4; i += stride)
        a[i] = make_float4(0.f, 0.f, 0.f, 0.f);
    for (int i = blockIdx.x * blockDim.x + threadIdx.x; i < nb; i += stride)
        b[i] = 0;
}

__global__ void k_count(const int* __restrict__ s0, const int* __restrict__ d0,
                        const int* __restrict__ s1, const int* __restrict__ d1,
                        int* __restrict__ ints) {
    int i = blockIdx.x * blockDim.x + threadIdx.x;
    if (i < E0V) {
        atomicAdd(ints + OFF_C_SRC0 + s0[i], 1);
        atomicAdd(ints + OFF_C_DST0 + d0[i], 1);
    } else {
        int j = i - E0V;
        if (j < E1V) {
            atomicAdd(ints + OFF_C_SRC1 + s1[j], 1);
            atomicAdd(ints + OFF_C_DST1 + d1[j], 1);
        }
    }
}

__global__ void k_norm(const int* __restrict__ ints, float* __restrict__ nrm) {
    int i = blockIdx.x * blockDim.x + threadIdx.x;
    if (i < N_CNT) nrm[i] = rsqrtf(fmaxf((float)ints[i], 1.0f));
}

__global__ void k_scan1(const int* __restrict__ cnt, int* __restrict__ rp,
                        int* __restrict__ part, int n) {
    __shared__ int sd[1024];
    int tid = threadIdx.x;
    int i = blockIdx.x * 1024 + tid;
    sd[tid] = (i < n) ? cnt[i] : 0;
    __syncthreads();
#pragma unroll
    for (int d = 1; d < 1024; d <<= 1) {
        int t = (tid >= d) ? sd[tid - d] : 0;
        __syncthreads();
        sd[tid] += t;
        __syncthreads();
    }
    if (i < n) rp[i + 1] = sd[tid];
    if (tid == 1023) part[blockIdx.x] = sd[1023];
}

__global__ void k_scan2(int* __restrict__ part, int nb, int* __restrict__ rp) {
    __shared__ int sd[128];
    int tid = threadIdx.x;
    sd[tid] = (tid < nb) ? part[tid] : 0;
    __syncthreads();
#pragma unroll
    for (int d = 1; d < 128; d <<= 1) {
        int t = (tid >= d) ? sd[tid - d] : 0;
        __syncthreads();
        sd[tid] += t;
        __syncthreads();
    }
    if (tid < nb) part[tid] = (tid == 0) ? 0 : sd[tid - 1];
    if (tid == 0) rp[0] = 0;
}

__global__ void k_scan3(int* __restrict__ rp, const int* __restrict__ part, int n) {
    int b = blockIdx.x;
    if (b == 0) return;
    int i = b * 1024 + threadIdx.x;
    if (i < n) rp[i + 1] += part[b];
}

__global__ void k_fill(const int* __restrict__ key, const int* __restrict__ val,
                       const int* __restrict__ rp, int* __restrict__ cur,
                       int* __restrict__ col, int E) {
    int i = blockIdx.x * blockDim.x + threadIdx.x;
    if (i < E) {
        int k = key[i];
        int pos = rp[k] + atomicAdd(cur + k, 1);
        col[pos] = val[i];
    }
}

// W [K, N] row-major -> Wt hi/lo [N, K] bf16 split (both layers in one kernel)
__global__ void k_wprep(const float* __restrict__ W1, const float* __restrict__ W2,
                        __nv_bfloat16* __restrict__ w1h, __nv_bfloat16* __restrict__ w1l,
                        __nv_bfloat16* __restrict__ w2h, __nv_bfloat16* __restrict__ w2l) {
    int i = blockIdx.x * blockDim.x + threadIdx.x;
    if (i < 512 * 512) {
        int n = i >> 9, k = i & 511;
        float v = W1[k * 512 + n];
        __nv_bfloat16 h = __float2bfloat16(v);
        w1h[i] = h;
        w1l[i] = __float2bfloat16(v - __bfloat162float(h));
    } else {
        int j = i - 512 * 512;
        if (j < 256 * 512) {
            int n = j >> 9, k = j & 511;
            float v = W2[k * 256 + n];
            __nv_bfloat16 h = __float2bfloat16(v);
            w2h[j] = h;
            w2l[j] = __float2bfloat16(v - __bfloat162float(h));
        }
    }
}

// A [M,512] f32 * rs[row] -> hi/lo bf16 [Mpad,512]; pad rows zero.
__global__ void k_convert(const float* __restrict__ A, const float* __restrict__ rs,
                          __nv_bfloat16* __restrict__ hi, __nv_bfloat16* __restrict__ lo,
                          int M, int Mpad) {
    int i = blockIdx.x * blockDim.x + threadIdx.x;   // float4 index
    int n4 = Mpad * 128;
    if (i >= n4) return;
    int row = i >> 7;
    float4 v = make_float4(0.f, 0.f, 0.f, 0.f);
    if (row < M) {
        v = reinterpret_cast<const float4*>(A)[i];
        float sc = rs[row];
        v.x *= sc; v.y *= sc; v.z *= sc; v.w *= sc;
    }
    __nv_bfloat16 hx = __float2bfloat16(v.x), hy = __float2bfloat16(v.y);
    __nv_bfloat16 hz = __float2bfloat16(v.z), hw = __float2bfloat16(v.w);
    __nv_bfloat162* hp = reinterpret_cast<__nv_bfloat162*>(hi) + i * 2;
    hp[0] = __nv_bfloat162(hx, hy);
    hp[1] = __nv_bfloat162(hz, hw);
    __nv_bfloat162* lp = reinterpret_cast<__nv_bfloat162*>(lo) + i * 2;
    lp[0] = __nv_bfloat162(__float2bfloat16(v.x - __bfloat162float(hx)),
                           __float2bfloat16(v.y - __bfloat162float(hy)));
    lp[1] = __nv_bfloat162(__float2bfloat16(v.z - __bfloat162float(hz)),
                           __float2bfloat16(v.w - __bfloat162float(hw)));
}

// ---------------- layer-1: CSR-by-src scatter --------------------------------
__global__ void k_scatter_src(const float* __restrict__ x,
                              const int* __restrict__ rp, const int* __restrict__ col,
                              const float* __restrict__ outn,
                              float* __restrict__ agg, int n_src) {
    int w = (blockIdx.x * blockDim.x + threadIdx.x) >> 5;
    int lane = threadIdx.x & 31;
    if (w >= n_src) return;
    int beg = rp[w], end = rp[w + 1];
    if (beg == end) return;
    float sc = outn[w];
    const float4* xp = reinterpret_cast<const float4*>(x) + (size_t)w * (IN_F / 4) + lane;
    float4 v0 = xp[0], v1 = xp[32], v2 = xp[64], v3 = xp[96];
    v0.x *= sc; v0.y *= sc; v0.z *= sc; v0.w *= sc;
    v1.x *= sc; v1.y *= sc; v1.z *= sc; v1.w *= sc;
    v2.x *= sc; v2.y *= sc; v2.z *= sc; v2.w *= sc;
    v3.x *= sc; v3.y *= sc; v3.z *= sc; v3.w *= sc;
    for (int e = beg; e < end; e++) {
        int d = __ldg(col + e);
        float* ap = agg + (size_t)d * IN_F + lane * 4;
        asm volatile("red.global.add.v4.f32 [%0], {%1, %2, %3, %4};"
                     :: "l"(ap), "f"(v0.x), "f"(v0.y), "f"(v0.z), "f"(v0.w) : "memory");
        asm volatile("red.global.add.v4.f32 [%0], {%1, %2, %3, %4};"
                     :: "l"(ap + 128), "f"(v1.x), "f"(v1.y), "f"(v1.z), "f"(v1.w) : "memory");
        asm volatile("red.global.add.v4.f32 [%0], {%1, %2, %3, %4};"
                     :: "l"(ap + 256), "f"(v2.x), "f"(v2.y), "f"(v2.z), "f"(v2.w) : "memory");
        asm volatile("red.global.add.v4.f32 [%0], {%1, %2, %3, %4};"
                     :: "l"(ap + 384), "f"(v3.x), "f"(v3.y), "f"(v3.z), "f"(v3.w) : "memory");
    }
}

// ---------------- layer-2: CSR-by-dst gather ---------------------------------
__global__ void k_gather_dst(const float* __restrict__ h,
                             const int* __restrict__ rp, const int* __restrict__ col,
                             const float* __restrict__ outn,
                             float* __restrict__ agg, int n_dst) {
    int w = (blockIdx.x * blockDim.x + threadIdx.x) >> 5;
    int lane = threadIdx.x & 31;
    if (w >= n_dst) return;
    int beg = rp[w], end = rp[w + 1];
    float4 a0 = make_float4(0.f, 0.f, 0.f, 0.f);
    float4 a1 = a0, a2 = a0, a3 = a0;
    for (int e = beg; e < end; e++) {
        int s = __ldg(col + e);
        float sc = __ldg(outn + s);
        const float4* hp = reinterpret_cast<const float4*>(h) + (size_t)s * (HID_F / 4) + lane;
        float4 v0 = __ldg(hp), v1 = __ldg(hp + 32), v2 = __ldg(hp + 64), v3 = __ldg(hp + 96);
        a0.x = fmaf(v0.x, sc, a0.x); a0.y = fmaf(v0.y, sc, a0.y);
        a0.z = fmaf(v0.z, sc, a0.z); a0.w = fmaf(v0.w, sc, a0.w);
        a1.x = fmaf(v1.x, sc, a1.x); a1.y = fmaf(v1.y, sc, a1.y);
        a1.z = fmaf(v1.z, sc, a1.z); a1.w = fmaf(v1.w, sc, a1.w);
        a2.x = fmaf(v2.x, sc, a2.x); a2.y = fmaf(v2.y, sc, a2.y);
        a2.z = fmaf(v2.z, sc, a2.z); a2.w = fmaf(v2.w, sc, a2.w);
        a3.x = fmaf(v3.x, sc, a3.x); a3.y = fmaf(v3.y, sc, a3.y);
        a3.z = fmaf(v3.z, sc, a3.z); a3.w = fmaf(v3.w, sc, a3.w);
    }
    float4* ap = reinterpret_cast<float4*>(agg) + (size_t)w * (HID_F / 4) + lane;
    ap[0] = a0; ap[32] = a1; ap[64] = a2; ap[96] = a3;
}

// ---------------- mma.sync bf16-split GEMM -----------------------------------
// C[128,128] block = relu( A[Mpad,512] @ (B[Nt,512])^T + bias ), hi/lo split.
// 256 threads = 8 warps (2x4), warp tile 64x32, BK=32, K=512 -> 16 iters.
#define PADK 40   // bf16 elements per smem row (80B, ldmatrix-phase conflict-free)

__device__ __forceinline__ void ldm4(uint32_t* f, uint32_t addr) {
    asm volatile("ldmatrix.sync.aligned.m8n8.x4.shared.b16 {%0,%1,%2,%3}, [%4];"
                 : "=r"(f[0]), "=r"(f[1]), "=r"(f[2]), "=r"(f[3]) : "r"(addr));
}

__device__ __forceinline__ void mma16816(float* c, const uint32_t* a, const uint32_t* b) {
    asm volatile("mma.sync.aligned.m16n8k16.row.col.f32.bf16.bf16.f32 "
                 "{%0,%1,%2,%3}, {%4,%5,%6,%7}, {%8,%9}, {%0,%1,%2,%3};"
                 : "+f"(c[0]), "+f"(c[1]), "+f"(c[2]), "+f"(c[3])
                 : "r"(a[0]), "r"(a[1]), "r"(a[2]), "r"(a[3]), "r"(b[0]), "r"(b[1]));
}

__global__ __launch_bounds__(256) void k_gemm_mma(
    const __nv_bfloat16* __restrict__ Ahi, const __nv_bfloat16* __restrict__ Alo,
    const __nv_bfloat16* __restrict__ Bhi, const __nv_bfloat16* __restrict__ Blo,
    const float* __restrict__ bias, float* __restrict__ C,
    int M, int Nt) {
    __shared__ __nv_bfloat16 sAh[128 * PADK], sAl[128 * PADK];
    __shared__ __nv_bfloat16 sBh[128 * PADK], sBl[128 * PADK];

    int tid = threadIdx.x;
    int wid = tid >> 5, lane = tid & 31;
    int wm = (wid >> 2) * 64;         // warp row offset (0,64)
    int wn = (wid & 3) * 32;          // warp col offset (0,32,64,96)
    int row0 = blockIdx.y * 128, col0 = blockIdx.x * 128;

    // global load slot: row r, 16-col half
    int lr = tid >> 1;
    int lh = (tid & 1) * 16;
    const int4* gAh = (const int4*)(Ahi + (size_t)(row0 + lr) * 512 + lh);
    const int4* gAl = (const int4*)(Alo + (size_t)(row0 + lr) * 512 + lh);
    const int4* gBh = (const int4*)(Bhi + (size_t)(col0 + lr) * 512 + lh);
    const int4* gBl = (const int4*)(Blo + (size_t)(col0 + lr) * 512 + lh);
    int4* tAh = (int4*)(sAh + lr * PADK + lh);
    int4* tAl = (int4*)(sAl + lr * PADK + lh);
    int4* tBh = (int4*)(sBh + lr * PADK + lh);
    int4* tBl = (int4*)(sBl + lr * PADK + lh);

    uint32_t uAh = (uint32_t)__cvta_generic_to_shared(sAh);
    uint32_t uAl = (uint32_t)__cvta_generic_to_shared(sAl);
    uint32_t uBh = (uint32_t)__cvta_generic_to_shared(sBh);
    uint32_t uBl = (uint32_t)__cvta_generic_to_shared(sBl);

    // ldmatrix lane address components
    int aRow = wm + (lane & 15);             // + mt*16
    int aCol = (lane >> 4) << 3;             // + ks
    int bRow = wn + (lane & 7) + ((lane >> 4) << 3);   // + ntp*16
    int bCol = ((lane >> 3) & 1) << 3;       // + ks

    float acc[4][4][4];
#pragma unroll
    for (int i = 0; i < 4; i++)
#pragma unroll
        for (int j = 0; j < 4; j++)
#pragma unroll
            for (int k = 0; k < 4; k++) acc[i][j][k] = 0.f;

    // prefetch chunk 0 (consecutive int4s in a row are +1 apart!)
    int4 rA0 = __ldg(gAh), rA1 = __ldg(gAh + 1);
    int4 rL0 = __ldg(gAl), rL1 = __ldg(gAl + 1);
    int4 rB0 = __ldg(gBh), rB1 = __ldg(gBh + 1);
    int4 rM0 = __ldg(gBl), rM1 = __ldg(gBl + 1);

    for (int c = 0; c < 16; c++) {
        tAh[0] = rA0; tAh[1] = rA1;
        tAl[0] = rL0; tAl[1] = rL1;
        tBh[0] = rB0; tBh[1] = rB1;
        tBl[0] = rM0; tBl[1] = rM1;
        __syncthreads();

        if (c + 1 < 16) {                 // prefetch next chunk during compute
            int g = (c + 1) * 4;
            rA0 = __ldg(gAh + g); rA1 = __ldg(gAh + g + 1);
            rL0 = __ldg(gAl + g); rL1 = __ldg(gAl + g + 1);
            rB0 = __ldg(gBh + g); rB1 = __ldg(gBh + g + 1);
            rM0 = __ldg(gBl + g); rM1 = __ldg(gBl + g + 1);
        }

#pragma unroll
        for (int ks = 0; ks < 32; ks += 16) {
            uint32_t ah[4][4], al[4][4], bh[4][2], bl[4][2];
#pragma unroll
            for (int mt = 0; mt < 4; mt++) {
                uint32_t off = ((uint32_t)((aRow + mt * 16) * PADK + ks + aCol)) * 2;
                ldm4(ah[mt], uAh + off);
                ldm4(al[mt], uAl + off);
            }
#pragma unroll
            for (int ntp = 0; ntp < 2; ntp++) {
                uint32_t off = ((uint32_t)((bRow + ntp * 16) * PADK + ks + bCol)) * 2;
                uint32_t t[4];
                ldm4(t, uBh + off);
                bh[ntp * 2][0] = t[0]; bh[ntp * 2][1] = t[1];
                bh[ntp * 2 + 1][0] = t[2]; bh[ntp * 2 + 1][1] = t[3];
                ldm4(t, uBl + off);
                bl[ntp * 2][0] = t[0]; bl[ntp * 2][1] = t[1];
                bl[ntp * 2 + 1][0] = t[2]; bl[ntp * 2 + 1][1] = t[3];
            }
#pragma unroll
            for (int mt = 0; mt < 4; mt++)
#pragma unroll
                for (int nt = 0; nt < 4; nt++) {
                    mma16816(acc[mt][nt], ah[mt], bh[nt]);
                    mma16816(acc[mt][nt], ah[mt], bl[nt]);
                    mma16816(acc[mt][nt], al[mt], bh[nt]);
                }
        }
        __syncthreads();
    }

    // epilogue: bias + relu, 2 floats per (mt,nt,half)
    int erow = row0 + wm + (lane >> 2);
    int ecol0 = col0 + wn + (lane & 3) * 2;
#pragma unroll
    for (int nt = 0; nt < 4; nt++) {
        int cc = ecol0 + nt * 8;
        float bx = __ldg(bias + cc), by = __ldg(bias + cc + 1);
#pragma unroll
        for (int mt = 0; mt < 4; mt++) {
            int r = erow + mt * 16;
            if (r < M) {
                float2 o;
                o.x = fmaxf(acc[mt][nt][0] + bx, 0.f);
                o.y = fmaxf(acc[mt][nt][1] + by, 0.f);
                *(float2*)(C + (size_t)r * Nt + cc) = o;
            }
            if (r + 8 < M) {
                float2 o;
                o.x = fmaxf(acc[mt][nt][2] + bx, 0.f);
                o.y = fmaxf(acc[mt][nt][3] + by, 0.f);
                *(float2*)(C + (size_t)(r + 8) * Nt + cc) = o;
            }
        }
    }
}

// ---------------- launch ----------------------------------------------------

extern "C" void kernel_launch(void* const* d_in, const int* in_sizes, int n_in,
                              void* d_out, int out_size) {
    const float* x    = (const float*)d_in[0];
    const int*   src0 = (const int*)d_in[1];
    const int*   dst0 = (const int*)d_in[2];
    const int*   src1 = (const int*)d_in[3];
    const int*   dst1 = (const int*)d_in[4];
    const float* W1   = (const float*)d_in[5];
    const float* b1   = (const float*)d_in[6];
    const float* W2   = (const float*)d_in[7];
    const float* b2   = (const float*)d_in[8];
    float* out = (float*)d_out;

    float *agg0, *h1, *agg1, *nrm;
    int *ints, *rp0, *rp1, *col0, *col1, *part;
    __nv_bfloat16 *a1h, *a1l, *a2h, *a2l, *w1h, *w1l, *w2h, *w2l;
    cudaGetSymbolAddress((void**)&agg0, g_agg0);
    cudaGetSymbolAddress((void**)&h1,   g_h1);
    cudaGetSymbolAddress((void**)&agg1, g_agg1);
    cudaGetSymbolAddress((void**)&nrm,  g_norm);
    cudaGetSymbolAddress((void**)&ints, g_ints);
    cudaGetSymbolAddress((void**)&rp0,  g_rp0);
    cudaGetSymbolAddress((void**)&rp1,  g_rp1);
    cudaGetSymbolAddress((void**)&col0, g_col0);
    cudaGetSymbolAddress((void**)&col1, g_col1);
    cudaGetSymbolAddress((void**)&part, g_part);
    cudaGetSymbolAddress((void**)&a1h, g_a1hi);
    cudaGetSymbolAddress((void**)&a1l, g_a1lo);
    cudaGetSymbolAddress((void**)&a2h, g_a2hi);
    cudaGetSymbolAddress((void**)&a2l, g_a2lo);
    cudaGetSymbolAddress((void**)&w1h, g_w1hi);
    cudaGetSymbolAddress((void**)&w1l, g_w1lo);
    cudaGetSymbolAddress((void**)&w2h, g_w2hi);
    cudaGetSymbolAddress((void**)&w2l, g_w2lo);

    const float* outn0 = nrm + OFF_C_SRC0;
    const float* din0  = nrm + OFF_C_DST0;
    const float* outn1 = nrm + OFF_C_SRC1;
    const float* din1  = nrm + OFF_C_DST1;

    // 1) zero agg0 + int counters
    k_zero2<<<2048, 256>>>((float4*)agg0, (int)((size_t)N_DST0 * IN_F / 4), ints, N_INTS);

    // 2) weight transpose + bf16 split
    k_wprep<<<(512 * 512 + 256 * 512 + 255) / 256, 256>>>(W1, W2, w1h, w1l, w2h, w2l);

    // 3) degree counts, norms
    k_count<<<(E0V + E1V + 255) / 256, 256>>>(src0, dst0, src1, dst1, ints);
    k_norm<<<(N_CNT + 255) / 256, 256>>>(ints, nrm);

    // 4) CSR layer-1 by src
    {
        int nb = (N_SRC0 + 1023) / 1024;
        k_scan1<<<nb, 1024>>>(ints + OFF_C_SRC0, rp0, part, N_SRC0);
        k_scan2<<<1, 128>>>(part, nb, rp0);
        k_scan3<<<nb, 1024>>>(rp0, part, N_SRC0);
        k_fill<<<(E0V + 255) / 256, 256>>>(src0, dst0, rp0, ints + OFF_CUR0, col0, E0V);
    }
    // 5) CSR layer-2 by dst
    {
        int nb = (N_DST1 + 1023) / 1024;
        k_scan1<<<nb, 1024>>>(ints + OFF_C_DST1, rp1, part, N_DST1);
        k_scan2<<<1, 128>>>(part, nb, rp1);
        k_scan3<<<nb, 1024>>>(rp1, part, N_DST1);
        k_fill<<<(E1V + 255) / 256, 256>>>(dst1, src1, rp1, ints + OFF_CUR1, col1, E1V);
    }

    // 6) layer-1 scatter into L2-resident agg0
    k_scatter_src<<<(N_SRC0 * 32 + 255) / 256, 256>>>(x, rp0, col0, outn0, agg0, N_SRC0);

    // 7) convert agg0*din0 -> bf16 hi/lo, then HMMA GEMM1 + bias + relu
    k_convert<<<(MPAD1 * 128 + 255) / 256, 256>>>(agg0, din0, a1h, a1l, N_DST0, MPAD1);
    {
        dim3 grid(HID_F / 128, MPAD1 / 128);   // (4, 157)
        k_gemm_mma<<<grid, 256>>>(a1h, a1l, w1h, w1l, b1, h1, N_DST0, HID_F);
    }

    // 8) layer-2 gather (h1 in L2)
    k_gather_dst<<<(N_DST1 * 32 + 255) / 256, 256>>>(h1, rp1, col1, outn1, agg1, N_DST1);

    // 9) convert agg1*din1 -> bf16 hi/lo, then HMMA GEMM2 + bias + relu
    k_convert<<<(MPAD2 * 128 + 255) / 256, 256>>>(agg1, din1, a2h, a2l, N_DST1, MPAD2);
    {
        dim3 grid(OUT_F / 128, MPAD2 / 128);   // (2, 32)
        k_gemm_mma<<<grid, 256>>>(a2h, a2l, w2h, w2l, b2, out, N_DST1, OUT_F);
    }
}

// round 8
// speedup vs baseline: 1.4647x; 1.0089x over previous
#include <cuda_runtime.h>
#include <cuda_bf16.h>
#include <cstdint>

#define N_SRC0 100000
#define N_DST0 20000
#define N_DST1 4000
#define E0V 640000
#define E1V 128000
#define IN_F 512
#define HID_F 512
#define OUT_F 256

#define MPAD1 20096          // 157 * 128
#define MPAD2 4096           // 32 * 128

// ---------------- scratch (device globals) ----------------------------------
__device__ float g_agg0[(size_t)N_DST0 * IN_F];
__device__ float g_h1[(size_t)N_DST0 * HID_F];
__device__ float g_agg1[(size_t)N_DST1 * HID_F];
__device__ float g_norm[N_SRC0 + N_DST0 + N_DST0 + N_DST1];

#define OFF_C_SRC0 0
#define OFF_C_DST0 (N_SRC0)
#define OFF_C_SRC1 (N_SRC0 + N_DST0)
#define OFF_C_DST1 (N_SRC0 + 2 * N_DST0)
#define N_CNT      (N_SRC0 + 2 * N_DST0 + N_DST1)
#define OFF_CUR0   N_CNT
#define OFF_CUR1   (N_CNT + N_SRC0)
#define N_INTS     (N_CNT + N_SRC0 + N_DST1)
__device__ int g_ints[N_INTS];

__device__ int g_rp0[N_SRC0 + 1];
__device__ int g_rp1[N_DST1 + 1];
__device__ int g_col0[E0V];
__device__ int g_col1[E1V];
__device__ int g_part[256];

// ---------------- utility kernels -------------------------------------------

__global__ void k_zero2(float4* __restrict__ a, int n4, int* __restrict__ b, int nb) {
    int stride = gridDim.x * blockDim.x;
    for (int i = blockIdx.x * blockDim.x + threadIdx.x; i < n4; i += stride)
        a[i] = make_float4(0.f, 0.f, 0.f, 0.f);
    for (int i = blockIdx.x * blockDim.x + threadIdx.x; i < nb; i += stride)
        b[i] = 0;
}

__global__ void k_count(const int* __restrict__ s0, const int* __restrict__ d0,
                        const int* __restrict__ s1, const int* __restrict__ d1,
                        int* __restrict__ ints) {
    int i = blockIdx.x * blockDim.x + threadIdx.x;
    if (i < E0V) {
        atomicAdd(ints + OFF_C_SRC0 + s0[i], 1);
        atomicAdd(ints + OFF_C_DST0 + d0[i], 1);
    } else {
        int j = i - E0V;
        if (j < E1V) {
            atomicAdd(ints + OFF_C_SRC1 + s1[j], 1);
            atomicAdd(ints + OFF_C_DST1 + d1[j], 1);
        }
    }
}

__global__ void k_norm(const int* __restrict__ ints, float* __restrict__ nrm) {
    int i = blockIdx.x * blockDim.x + threadIdx.x;
    if (i < N_CNT) nrm[i] = rsqrtf(fmaxf((float)ints[i], 1.0f));
}

__global__ void k_scan1(const int* __restrict__ cnt, int* __restrict__ rp,
                        int* __restrict__ part, int n) {
    __shared__ int sd[1024];
    int tid = threadIdx.x;
    int i = blockIdx.x * 1024 + tid;
    sd[tid] = (i < n) ? cnt[i] : 0;
    __syncthreads();
#pragma unroll
    for (int d = 1; d < 1024; d <<= 1) {
        int t = (tid >= d) ? sd[tid - d] : 0;
        __syncthreads();
        sd[tid] += t;
        __syncthreads();
    }
    if (i < n) rp[i + 1] = sd[tid];
    if (tid == 1023) part[blockIdx.x] = sd[1023];
}

__global__ void k_scan2(int* __restrict__ part, int nb, int* __restrict__ rp) {
    __shared__ int sd[128];
    int tid = threadIdx.x;
    sd[tid] = (tid < nb) ? part[tid] : 0;
    __syncthreads();
#pragma unroll
    for (int d = 1; d < 128; d <<= 1) {
        int t = (tid >= d) ? sd[tid - d] : 0;
        __syncthreads();
        sd[tid] += t;
        __syncthreads();
    }
    if (tid < nb) part[tid] = (tid == 0) ? 0 : sd[tid - 1];
    if (tid == 0) rp[0] = 0;
}

__global__ void k_scan3(int* __restrict__ rp, const int* __restrict__ part, int n) {
    int b = blockIdx.x;
    if (b == 0) return;
    int i = b * 1024 + threadIdx.x;
    if (i < n) rp[i + 1] += part[b];
}

__global__ void k_fill(const int* __restrict__ key, const int* __restrict__ val,
                       const int* __restrict__ rp, int* __restrict__ cur,
                       int* __restrict__ col, int E) {
    int i = blockIdx.x * blockDim.x + threadIdx.x;
    if (i < E) {
        int k = key[i];
        int pos = rp[k] + atomicAdd(cur + k, 1);
        col[pos] = val[i];
    }
}

// ---------------- layer-1: CSR-by-src scatter --------------------------------
__global__ void k_scatter_src(const float* __restrict__ x,
                              const int* __restrict__ rp, const int* __restrict__ col,
                              const float* __restrict__ outn,
                              float* __restrict__ agg, int n_src) {
    int w = (blockIdx.x * blockDim.x + threadIdx.x) >> 5;
    int lane = threadIdx.x & 31;
    if (w >= n_src) return;
    int beg = rp[w], end = rp[w + 1];
    if (beg == end) return;
    float sc = outn[w];
    const float4* xp = reinterpret_cast<const float4*>(x) + (size_t)w * (IN_F / 4) + lane;
    float4 v0 = xp[0], v1 = xp[32], v2 = xp[64], v3 = xp[96];
    v0.x *= sc; v0.y *= sc; v0.z *= sc; v0.w *= sc;
    v1.x *= sc; v1.y *= sc; v1.z *= sc; v1.w *= sc;
    v2.x *= sc; v2.y *= sc; v2.z *= sc; v2.w *= sc;
    v3.x *= sc; v3.y *= sc; v3.z *= sc; v3.w *= sc;
    for (int e = beg; e < end; e++) {
        int d = __ldg(col + e);
        float* ap = agg + (size_t)d * IN_F + lane * 4;
        asm volatile("red.global.add.v4.f32 [%0], {%1, %2, %3, %4};"
                     :: "l"(ap), "f"(v0.x), "f"(v0.y), "f"(v0.z), "f"(v0.w) : "memory");
        asm volatile("red.global.add.v4.f32 [%0], {%1, %2, %3, %4};"
                     :: "l"(ap + 128), "f"(v1.x), "f"(v1.y), "f"(v1.z), "f"(v1.w) : "memory");
        asm volatile("red.global.add.v4.f32 [%0], {%1, %2, %3, %4};"
                     :: "l"(ap + 256), "f"(v2.x), "f"(v2.y), "f"(v2.z), "f"(v2.w) : "memory");
        asm volatile("red.global.add.v4.f32 [%0], {%1, %2, %3, %4};"
                     :: "l"(ap + 384), "f"(v3.x), "f"(v3.y), "f"(v3.z), "f"(v3.w) : "memory");
    }
}

// ---------------- layer-2: CSR-by-dst gather ---------------------------------
__global__ void k_gather_dst(const float* __restrict__ h,
                             const int* __restrict__ rp, const int* __restrict__ col,
                             const float* __restrict__ outn,
                             float* __restrict__ agg, int n_dst) {
    int w = (blockIdx.x * blockDim.x + threadIdx.x) >> 5;
    int lane = threadIdx.x & 31;
    if (w >= n_dst) return;
    int beg = rp[w], end = rp[w + 1];
    float4 a0 = make_float4(0.f, 0.f, 0.f, 0.f);
    float4 a1 = a0, a2 = a0, a3 = a0;
    for (int e = beg; e < end; e++) {
        int s = __ldg(col + e);
        float sc = __ldg(outn + s);
        const float4* hp = reinterpret_cast<const float4*>(h) + (size_t)s * (HID_F / 4) + lane;
        float4 v0 = __ldg(hp), v1 = __ldg(hp + 32), v2 = __ldg(hp + 64), v3 = __ldg(hp + 96);
        a0.x = fmaf(v0.x, sc, a0.x); a0.y = fmaf(v0.y, sc, a0.y);
        a0.z = fmaf(v0.z, sc, a0.z); a0.w = fmaf(v0.w, sc, a0.w);
        a1.x = fmaf(v1.x, sc, a1.x); a1.y = fmaf(v1.y, sc, a1.y);
        a1.z = fmaf(v1.z, sc, a1.z); a1.w = fmaf(v1.w, sc, a1.w);
        a2.x = fmaf(v2.x, sc, a2.x); a2.y = fmaf(v2.y, sc, a2.y);
        a2.z = fmaf(v2.z, sc, a2.z); a2.w = fmaf(v2.w, sc, a2.w);
        a3.x = fmaf(v3.x, sc, a3.x); a3.y = fmaf(v3.y, sc, a3.y);
        a3.z = fmaf(v3.z, sc, a3.z); a3.w = fmaf(v3.w, sc, a3.w);
    }
    float4* ap = reinterpret_cast<float4*>(agg) + (size_t)w * (HID_F / 4) + lane;
    ap[0] = a0; ap[32] = a1; ap[64] = a2; ap[96] = a3;
}

// ---------------- fused fp32->bf16-split HMMA GEMM ---------------------------
// C[128,128] = relu( (A[M,512]*rs) @ W[512,Nt] + bias ), split hi/lo, 3 products.
// A staged row-major [128][32] (PADK), W staged K-major [32][128] (PADN) and
// consumed via ldmatrix.trans. Double-buffered SMEM, one sync per K-chunk.
#define PADK 40    // A smem row stride (elems)
#define PADN 136   // B smem row stride (elems)
#define SZ_A 10240                 // 128*PADK*2
#define SZ_B 8704                  // 32*PADN*2
#define STAGE_BYTES (2 * SZ_A + 2 * SZ_B)          // 37888
#define GSM_TOTAL (2 * STAGE_BYTES)                // 75776
#define O_AH 0
#define O_AL SZ_A
#define O_BH (2 * SZ_A)
#define O_BL (2 * SZ_A + SZ_B)

__device__ __forceinline__ void ldm4(uint32_t* f, uint32_t addr) {
    asm volatile("ldmatrix.sync.aligned.m8n8.x4.shared.b16 {%0,%1,%2,%3}, [%4];"
                 : "=r"(f[0]), "=r"(f[1]), "=r"(f[2]), "=r"(f[3]) : "r"(addr));
}
__device__ __forceinline__ void ldm4t(uint32_t* f, uint32_t addr) {
    asm volatile("ldmatrix.sync.aligned.m8n8.x4.trans.shared.b16 {%0,%1,%2,%3}, [%4];"
                 : "=r"(f[0]), "=r"(f[1]), "=r"(f[2]), "=r"(f[3]) : "r"(addr));
}
__device__ __forceinline__ void mma16816(float* c, const uint32_t* a, const uint32_t* b) {
    asm volatile("mma.sync.aligned.m16n8k16.row.col.f32.bf16.bf16.f32 "
                 "{%0,%1,%2,%3}, {%4,%5,%6,%7}, {%8,%9}, {%0,%1,%2,%3};"
                 : "+f"(c[0]), "+f"(c[1]), "+f"(c[2]), "+f"(c[3])
                 : "r"(a[0]), "r"(a[1]), "r"(a[2]), "r"(a[3]), "r"(b[0]), "r"(b[1]));
}

__device__ __forceinline__ void cvt_hilo(float4 v, uint2& h, uint2& l) {
    __nv_bfloat16 hx = __float2bfloat16(v.x), hy = __float2bfloat16(v.y);
    __nv_bfloat16 hz = __float2bfloat16(v.z), hw = __float2bfloat16(v.w);
    __nv_bfloat162 h0(hx, hy), h1(hz, hw);
    __nv_bfloat162 l0(__float2bfloat16(v.x - __bfloat162float(hx)),
                      __float2bfloat16(v.y - __bfloat162float(hy)));
    __nv_bfloat162 l1(__float2bfloat16(v.z - __bfloat162float(hz)),
                      __float2bfloat16(v.w - __bfloat162float(hw)));
    h.x = *reinterpret_cast<uint32_t*>(&h0);
    h.y = *reinterpret_cast<uint32_t*>(&h1);
    l.x = *reinterpret_cast<uint32_t*>(&l0);
    l.y = *reinterpret_cast<uint32_t*>(&l1);
}

__global__ __launch_bounds__(256) void k_gemm_f(
    const float* __restrict__ A, const float* __restrict__ rs,
    const float* __restrict__ W, const float* __restrict__ bias,
    float* __restrict__ C, int M, int Nt) {
    extern __shared__ char smem[];
    int tid = threadIdx.x;
    int wid = tid >> 5, lane = tid & 31;
    int wm = (wid >> 2) * 64;
    int wn = (wid & 3) * 32;
    int row0 = blockIdx.y * 128, col0 = blockIdx.x * 128;

    // A staging slot: row, 16-col half; 4 float4s per thread
    int sr = tid >> 1;
    int sk = (tid & 1) * 16;
    int rowA = row0 + sr;
    bool aval = rowA < M;
    float scA = aval ? __ldg(rs + rowA) : 0.f;
    const float* gA = A + (size_t)(aval ? rowA : 0) * 512 + sk;
    // B staging slot: k row, 16-wide n group; 4 float4s per thread
    int bk = tid >> 3;
    int bn = (tid & 7) * 16;
    const float* gW = W + (size_t)bk * Nt + col0 + bn;

    uint32_t ubase = (uint32_t)__cvta_generic_to_shared(smem);

    // ldmatrix lane components
    int aRow = wm + (lane & 15);
    int aCol = (lane >> 4) << 3;
    int kIdx = (lane & 7) + (((lane >> 3) & 1) << 3);   // B trans: k within 16
    int nOff = (lane >> 4) << 3;                        // B trans: n-block 0/8

    float acc[4][4][4];
#pragma unroll
    for (int i = 0; i < 4; i++)
#pragma unroll
        for (int j = 0; j < 4; j++)
#pragma unroll
            for (int k = 0; k < 4; k++) acc[i][j][k] = 0.f;

    // ---- stage chunk 0 into buffer 0
    {
        char* st = smem;
#pragma unroll
        for (int j = 0; j < 4; j++) {
            float4 va = aval ? __ldg((const float4*)(gA + 4 * j)) : make_float4(0, 0, 0, 0);
            va.x *= scA; va.y *= scA; va.z *= scA; va.w *= scA;
            uint2 h, l;
            cvt_hilo(va, h, l);
            int off = sr * PADK + sk + 4 * j;
            *(uint2*)(st + O_AH + off * 2) = h;
            *(uint2*)(st + O_AL + off * 2) = l;
        }
#pragma unroll
        for (int j = 0; j < 4; j++) {
            float4 vb = __ldg((const float4*)(gW + 4 * j));
            uint2 h, l;
            cvt_hilo(vb, h, l);
            int off = bk * PADN + bn + 4 * j;
            *(uint2*)(st + O_BH + off * 2) = h;
            *(uint2*)(st + O_BL + off * 2) = l;
        }
    }
    __syncthreads();

    for (int c = 0; c < 16; c++) {
        int buf = c & 1;
        uint32_t ub = ubase + buf * STAGE_BYTES;

        // issue next-chunk global loads first (latency hidden by MMAs)
        float4 pa[4], pb[4];
        if (c < 15) {
            int ka = (c + 1) * 32;
#pragma unroll
            for (int j = 0; j < 4; j++)
                pa[j] = aval ? __ldg((const float4*)(gA + ka + 4 * j))
                             : make_float4(0, 0, 0, 0);
#pragma unroll
            for (int j = 0; j < 4; j++)
                pb[j] = __ldg((const float4*)(gW + (size_t)(c + 1) * 32 * Nt + 4 * j));
        }

#pragma unroll
        for (int ks = 0; ks < 32; ks += 16) {
            uint32_t ah[4][4], al[4][4], bh[4][2], bl[4][2];
#pragma unroll
            for (int mt = 0; mt < 4; mt++) {
                uint32_t off = ((uint32_t)((aRow + mt * 16) * PADK + ks + aCol)) * 2;
                ldm4(ah[mt], ub + O_AH + off);
                ldm4(al[mt], ub + O_AL + off);
            }
#pragma unroll
            for (int ntp = 0; ntp < 2; ntp++) {
                uint32_t off = ((uint32_t)((ks + kIdx) * PADN + wn + ntp * 16 + nOff)) * 2;
                uint32_t t[4];
                ldm4t(t, ub + O_BH + off);
                bh[ntp * 2][0] = t[0]; bh[ntp * 2][1] = t[1];
                bh[ntp * 2 + 1][0] = t[2]; bh[ntp * 2 + 1][1] = t[3];
                ldm4t(t, ub + O_BL + off);
                bl[ntp * 2][0] = t[0]; bl[ntp * 2][1] = t[1];
                bl[ntp * 2 + 1][0] = t[2]; bl[ntp * 2 + 1][1] = t[3];
            }
#pragma unroll
            for (int mt = 0; mt < 4; mt++)
#pragma unroll
                for (int nt = 0; nt < 4; nt++) {
                    mma16816(acc[mt][nt], ah[mt], bh[nt]);
                    mma16816(acc[mt][nt], ah[mt], bl[nt]);
                    mma16816(acc[mt][nt], al[mt], bh[nt]);
                }
        }

        // convert + store next chunk into other buffer
        if (c < 15) {
            char* st = smem + (buf ^ 1) * STAGE_BYTES;
#pragma unroll
            for (int j = 0; j < 4; j++) {
                float4 va = pa[j];
                va.x *= scA; va.y *= scA; va.z *= scA; va.w *= scA;
                uint2 h, l;
                cvt_hilo(va, h, l);
                int off = sr * PADK + sk + 4 * j;
                *(uint2*)(st + O_AH + off * 2) = h;
                *(uint2*)(st + O_AL + off * 2) = l;
            }
#pragma unroll
            for (int j = 0; j < 4; j++) {
                uint2 h, l;
                cvt_hilo(pb[j], h, l);
                int off = bk * PADN + bn + 4 * j;
                *(uint2*)(st + O_BH + off * 2) = h;
                *(uint2*)(st + O_BL + off * 2) = l;
            }
        }
        __syncthreads();
    }

    // epilogue: bias + relu
    int erow = row0 + wm + (lane >> 2);
    int ecol0 = col0 + wn + (lane & 3) * 2;
#pragma unroll
    for (int nt = 0; nt < 4; nt++) {
        int cc = ecol0 + nt * 8;
        float bx = __ldg(bias + cc), by = __ldg(bias + cc + 1);
#pragma unroll
        for (int mt = 0; mt < 4; mt++) {
            int r = erow + mt * 16;
            if (r < M) {
                float2 o;
                o.x = fmaxf(acc[mt][nt][0] + bx, 0.f);
                o.y = fmaxf(acc[mt][nt][1] + by, 0.f);
                *(float2*)(C + (size_t)r * Nt + cc) = o;
            }
            if (r + 8 < M) {
                float2 o;
                o.x = fmaxf(acc[mt][nt][2] + bx, 0.f);
                o.y = fmaxf(acc[mt][nt][3] + by, 0.f);
                *(float2*)(C + (size_t)(r + 8) * Nt + cc) = o;
            }
        }
    }
}

// ---------------- launch ----------------------------------------------------

extern "C" void kernel_launch(void* const* d_in, const int* in_sizes, int n_in,
                              void* d_out, int out_size) {
    const float* x    = (const float*)d_in[0];
    const int*   src0 = (const int*)d_in[1];
    const int*   dst0 = (const int*)d_in[2];
    const int*   src1 = (const int*)d_in[3];
    const int*   dst1 = (const int*)d_in[4];
    const float* W1   = (const float*)d_in[5];
    const float* b1   = (const float*)d_in[6];
    const float* W2   = (const float*)d_in[7];
    const float* b2   = (const float*)d_in[8];
    float* out = (float*)d_out;

    float *agg0, *h1, *agg1, *nrm;
    int *ints, *rp0, *rp1, *col0, *col1, *part;
    cudaGetSymbolAddress((void**)&agg0, g_agg0);
    cudaGetSymbolAddress((void**)&h1,   g_h1);
    cudaGetSymbolAddress((void**)&agg1, g_agg1);
    cudaGetSymbolAddress((void**)&nrm,  g_norm);
    cudaGetSymbolAddress((void**)&ints, g_ints);
    cudaGetSymbolAddress((void**)&rp0,  g_rp0);
    cudaGetSymbolAddress((void**)&rp1,  g_rp1);
    cudaGetSymbolAddress((void**)&col0, g_col0);
    cudaGetSymbolAddress((void**)&col1, g_col1);
    cudaGetSymbolAddress((void**)&part, g_part);

    cudaFuncSetAttribute(k_gemm_f, cudaFuncAttributeMaxDynamicSharedMemorySize, GSM_TOTAL);

    const float* outn0 = nrm + OFF_C_SRC0;
    const float* din0  = nrm + OFF_C_DST0;
    const float* outn1 = nrm + OFF_C_SRC1;
    const float* din1  = nrm + OFF_C_DST1;

    // 1) zero agg0 + int counters
    k_zero2<<<2048, 256>>>((float4*)agg0, (int)((size_t)N_DST0 * IN_F / 4), ints, N_INTS);

    // 2) degree counts, norms
    k_count<<<(E0V + E1V + 255) / 256, 256>>>(src0, dst0, src1, dst1, ints);
    k_norm<<<(N_CNT + 255) / 256, 256>>>(ints, nrm);

    // 3) CSR layer-1 by src
    {
        int nb = (N_SRC0 + 1023) / 1024;
        k_scan1<<<nb, 1024>>>(ints + OFF_C_SRC0, rp0, part, N_SRC0);
        k_scan2<<<1, 128>>>(part, nb, rp0);
        k_scan3<<<nb, 1024>>>(rp0, part, N_SRC0);
        k_fill<<<(E0V + 255) / 256, 256>>>(src0, dst0, rp0, ints + OFF_CUR0, col0, E0V);
    }
    // 4) CSR layer-2 by dst
    {
        int nb = (N_DST1 + 1023) / 1024;
        k_scan1<<<nb, 1024>>>(ints + OFF_C_DST1, rp1, part, N_DST1);
        k_scan2<<<1, 128>>>(part, nb, rp1);
        k_scan3<<<nb, 1024>>>(rp1, part, N_DST1);
        k_fill<<<(E1V + 255) / 256, 256>>>(dst1, src1, rp1, ints + OFF_CUR1, col1, E1V);
    }

    // 5) layer-1 scatter into L2-resident agg0
    k_scatter_src<<<(N_SRC0 * 32 + 255) / 256, 256>>>(x, rp0, col0, outn0, agg0, N_SRC0);

    // 6) fused GEMM1: h1 = relu((agg0*din0) @ W1 + b1)
    {
        dim3 grid(HID_F / 128, MPAD1 / 128);   // (4, 157)
        k_gemm_f<<<grid, 256, GSM_TOTAL>>>(agg0, din0, W1, b1, h1, N_DST0, HID_F);
    }

    // 7) layer-2 gather (h1 in L2)
    k_gather_dst<<<(N_DST1 * 32 + 255) / 256, 256>>>(h1, rp1, col1, outn1, agg1, N_DST1);

    // 8) fused GEMM2: out = relu((agg1*din1) @ W2 + b2)
    {
        dim3 grid(OUT_F / 128, MPAD2 / 128);   // (2, 32)
        k_gemm_f<<<grid, 256, GSM_TOTAL>>>(agg1, din1, W2, b2, out, N_DST1, OUT_F);
    }
}